// round 9
// baseline (speedup 1.0000x reference)
#include <cuda_runtime.h>
#include <cstdint>
#include <math.h>

#define D_DIM   2048
#define E_DIM   64
#define TOPK    2
#define M_TILE  128
#define KC      32
#define NCHUNK  (D_DIM / KC)    /* 64 */
#define THREADS 256
#define ROWB    320             /* expert-row stride in stage: conflict-free LDS */
#define STAGE   (64 * ROWB)     /* 20480 B */
#define LG_STRIDE 65
#define SMEM_TOTAL (2 * STAGE)  /* 40960 >= logits 128*65*4 = 33280 */
#define TAU     1e-4f

__device__ __forceinline__ uint32_t smem_u32(const void* p) {
    uint32_t a;
    asm("{ .reg .u64 t; cvta.to.shared.u64 t, %1; cvt.u32.u64 %0, t; }" : "=r"(a) : "l"(p));
    return a;
}
__device__ __forceinline__ uint32_t f2tf32(float v) {
    uint32_t r;
    asm("cvt.rna.tf32.f32 %0, %1;" : "=r"(r) : "f"(v));
    return r;
}
__device__ __forceinline__ void mma_tf32(float* d, const uint32_t* a, uint32_t b0, uint32_t b1) {
    asm volatile(
        "mma.sync.aligned.m16n8k8.row.col.f32.tf32.tf32.f32 "
        "{%0,%1,%2,%3},{%4,%5,%6,%7},{%8,%9},{%0,%1,%2,%3};"
        : "+f"(d[0]), "+f"(d[1]), "+f"(d[2]), "+f"(d[3])
        : "r"(a[0]), "r"(a[1]), "r"(a[2]), "r"(a[3]), "r"(b0), "r"(b1));
}

extern __shared__ char smem[];

__global__ __launch_bounds__(THREADS, 1) void router_mma_kernel(
    const float* __restrict__ x, const float* __restrict__ W,
    float* __restrict__ out, int T)
{
    const uint32_t sb = smem_u32(smem);
    const int tid  = threadIdx.x;
    const int lane = tid & 31;
    const int wid  = tid >> 5;
    const int t0   = blockIdx.x * M_TILE;
    const int r    = lane >> 2;       // fragment row / expert-in-octet
    const int c    = lane & 3;        // fragment k index
    const int mq   = wid >> 1;        // m-quadrant: rows mq*32 .. +31
    const int nh   = wid & 1;         // n-half: experts nh*32 .. +31

    // ---- W loader mapping: thread -> (expert we, k-group g4 of 8) ----
    const int we = tid >> 2;          // 0..63
    const int g4 = tid & 3;           // 0..3
    const float* wp = W + (size_t)we * D_DIM + g4 * 8;

    // ---- A row pointers: warp owns rows mq*32 .. +31 ----
    const float* xr[4];
#pragma unroll
    for (int q = 0; q < 4; ++q)       // q = mt*2 + row2: rows mt*16 + row2*8 + r
        xr[q] = x + (size_t)(t0 + mq * 32 + (q >> 1) * 16 + (q & 1) * 8 + r) * D_DIM;

    float acc[2][4][4];
#pragma unroll
    for (int mt = 0; mt < 2; ++mt)
#pragma unroll
        for (int nt = 0; nt < 4; ++nt)
#pragma unroll
            for (int d = 0; d < 4; ++d) acc[mt][nt][d] = 0.f;

    float4 wv[2];       // W chunk in flight (8 k-values for expert we)
    float  ar[2][32];   // A double buffer: [buf][mt*16 + g*4 + pos]

#define LOAD_W(kc)                                                            \
    {  wv[0] = *(const float4*)(wp + (kc) * KC);                              \
       wv[1] = *(const float4*)(wp + (kc) * KC + 4); }

    // store wv into stage s: chunk (g4, m) at we*ROWB + g4*64 + m*16,
    // 16B = {hi_m, lo_m, hi_{m+4}, lo_{m+4}}; store order rotated by we&1
    // to cut STS bank conflicts 4-way -> 2-way.
#define STS_W(s)                                                              \
    {  float vq[8] = {wv[0].x, wv[0].y, wv[0].z, wv[0].w,                     \
                      wv[1].x, wv[1].y, wv[1].z, wv[1].w};                    \
       uint32_t hi[8], lo[8];                                                 \
       _Pragma("unroll")                                                      \
       for (int q = 0; q < 8; ++q) {                                          \
           hi[q] = f2tf32(vq[q]);                                             \
           lo[q] = f2tf32(vq[q] - __uint_as_float(hi[q]));                    \
       }                                                                      \
       _Pragma("unroll")                                                      \
       for (int ml = 0; ml < 4; ++ml) {                                       \
           int m = ml ^ (we & 1);                                             \
           uint32_t addr = sb + (s) * STAGE                                   \
                         + (uint32_t)(we * ROWB + g4 * 64 + m * 16);          \
           asm volatile("st.shared.v4.b32 [%0], {%1,%2,%3,%4};"               \
               :: "r"(addr), "r"(hi[m]), "r"(lo[m]),                          \
                  "r"(hi[m + 4]), "r"(lo[m + 4]) : "memory");                 \
       } }

#define LOAD_A(kc, b)                                                         \
    {  _Pragma("unroll")                                                      \
       for (int mt = 0; mt < 2; ++mt)                                         \
       _Pragma("unroll")                                                      \
       for (int g = 0; g < 4; ++g)                                            \
       _Pragma("unroll")                                                      \
       for (int pos = 0; pos < 4; ++pos)                                      \
           ar[b][mt * 16 + g * 4 + pos] =                                     \
               xr[mt * 2 + (pos & 1)][(kc) * KC + g * 8 + c + (pos >> 1) * 4]; }

#define COMPUTE(s, b)                                                         \
    {  _Pragma("unroll")                                                      \
       for (int g = 0; g < 4; ++g) {                                          \
           uint32_t ah[2][4], al[2][4];                                       \
           _Pragma("unroll")                                                  \
           for (int mt = 0; mt < 2; ++mt)                                     \
           _Pragma("unroll")                                                  \
           for (int pos = 0; pos < 4; ++pos) {                                \
               float v = ar[b][mt * 16 + g * 4 + pos];                        \
               ah[mt][pos] = f2tf32(v);                                       \
               al[mt][pos] = f2tf32(v - __uint_as_float(ah[mt][pos]));        \
           }                                                                  \
           _Pragma("unroll")                                                  \
           for (int nt = 0; nt < 4; ++nt) {                                   \
               uint32_t bq[4];                                                \
               uint32_t addr = sb + (s) * STAGE                               \
                   + (uint32_t)((nh * 32 + nt * 8 + r) * ROWB                 \
                   + g * 64 + c * 16);                                        \
               asm volatile("ld.shared.v4.b32 {%0,%1,%2,%3}, [%4];"           \
                   : "=r"(bq[0]), "=r"(bq[1]), "=r"(bq[2]), "=r"(bq[3])       \
                   : "r"(addr));                                              \
               _Pragma("unroll")                                              \
               for (int mt = 0; mt < 2; ++mt) {                               \
                   mma_tf32(acc[mt][nt], ah[mt], bq[0], bq[2]);               \
                   mma_tf32(acc[mt][nt], ah[mt], bq[1], bq[3]);               \
                   mma_tf32(acc[mt][nt], al[mt], bq[0], bq[2]);               \
               } } } }

    // -------- prologue --------
    LOAD_W(0);
    STS_W(0);
    LOAD_W(1);
    LOAD_A(0, 0);
    __syncthreads();

    // -------- main loop --------
    for (int kc = 0; kc < NCHUNK; ++kc) {
        const int s = kc & 1;
        if (kc + 1 < NCHUNK) {
            LOAD_A(kc + 1, s ^ 1);
            STS_W(s ^ 1);                 // wv holds chunk kc+1
        }
        if (kc + 2 < NCHUNK) LOAD_W(kc + 2);
        __syncthreads();                  // stage s^1 stores visible next iter
        COMPUTE(s, s);
        __syncthreads();                  // stage s reads done before overwrite
    }

    // -------- dump logits to smem (stride 65: conflict-free column scans) ----
    float* lg = (float*)smem;
#pragma unroll
    for (int mt = 0; mt < 2; ++mt)
#pragma unroll
        for (int nt = 0; nt < 4; ++nt) {
            int row = mq * 32 + mt * 16 + r;
            int col = nh * 32 + nt * 8 + c * 2;
            lg[row * LG_STRIDE + col]           = acc[mt][nt][0];
            lg[row * LG_STRIDE + col + 1]       = acc[mt][nt][1];
            lg[(row + 8) * LG_STRIDE + col]     = acc[mt][nt][2];
            lg[(row + 8) * LG_STRIDE + col + 1] = acc[mt][nt][3];
        }
    __syncthreads();

    // -------- per-token epilogue: threads 0..127, one per token --------
    if (tid < M_TILE) {
        const float* lrow = &lg[tid * LG_STRIDE];

        // top-4 scan ('>' keeps lower index first on ties, matching lax.top_k)
        float m0 = -INFINITY, m1 = -INFINITY, m2 = -INFINITY, m3 = -INFINITY;
        int i0 = 0, i1 = 0, i2 = 0, i3 = 0;
#pragma unroll 8
        for (int e = 0; e < E_DIM; ++e) {
            float v = lrow[e];
            if (v > m0)      { m3=m2;i3=i2; m2=m1;i2=i1; m1=m0;i1=i0; m0=v;i0=e; }
            else if (v > m1) { m3=m2;i3=i2; m2=m1;i2=i1; m1=v;i1=e; }
            else if (v > m2) { m3=m2;i3=i2; m2=v;i2=e; }
            else if (v > m3) { m3=v;i3=e; }
        }

        // fp64 fixup for near-ties (ordering becomes exact)
        bool flag = (m0 - m1 < TAU) || (m1 - m2 < TAU) || (m2 - m3 < TAU);
        unsigned bal = __ballot_sync(0xFFFFFFFFu, flag);
        while (bal) {
            int src = __ffs(bal) - 1;
            bal &= bal - 1;
            int tt = t0 + (wid << 5) + src;
            int e4[4];
            e4[0] = __shfl_sync(0xFFFFFFFFu, i0, src);
            e4[1] = __shfl_sync(0xFFFFFFFFu, i1, src);
            e4[2] = __shfl_sync(0xFFFFFFFFu, i2, src);
            e4[3] = __shfl_sync(0xFFFFFFFFu, i3, src);
            double s4[4] = {0.0, 0.0, 0.0, 0.0};
            const float* xrow2 = x + (size_t)tt * D_DIM;
            for (int k = lane; k < D_DIM; k += 32) {
                double xv = (double)xrow2[k];
#pragma unroll
                for (int j = 0; j < 4; ++j)
                    s4[j] += xv * (double)W[(size_t)e4[j] * D_DIM + k];
            }
#pragma unroll
            for (int off = 16; off > 0; off >>= 1)
#pragma unroll
                for (int j = 0; j < 4; ++j)
                    s4[j] += __shfl_xor_sync(0xFFFFFFFFu, s4[j], off);
            if (lane == src) {
                for (int a = 0; a < 3; ++a)
                    for (int b = 0; b < 3 - a; ++b)
                        if (s4[b + 1] > s4[b]) {
                            double td = s4[b]; s4[b] = s4[b + 1]; s4[b + 1] = td;
                            int ti = e4[b]; e4[b] = e4[b + 1]; e4[b + 1] = ti;
                        }
                i0 = e4[0];
                i1 = e4[1];
            }
        }

        // softmax + outputs
        float ssum = 0.f;
#pragma unroll 8
        for (int e = 0; e < E_DIM; ++e) ssum += expf(lrow[e] - m0);
        const float inv  = 1.0f / ssum;
        const float p1   = expf(lrow[i0] - m0) * inv;
        const float p2   = expf(lrow[i1] - m0) * inv;
        const float rinv = 1.0f / (p1 + p2);

        const int t = t0 + tid;
        const size_t TT = (size_t)T;
        float* mask_o = out + (size_t)t * E_DIM;
        float* idx_o  = out + TT * E_DIM + (size_t)t * TOPK;
        float* rp_o   = out + TT * (E_DIM + TOPK) + (size_t)t * E_DIM;
        float* p_o    = out + TT * (2 * E_DIM + TOPK) + (size_t)t * E_DIM;

        idx_o[0] = (float)i0;
        idx_o[1] = (float)i1;

#pragma unroll 4
        for (int e = 0; e < E_DIM; e += 4) {
            float4 pv, mv, rv;
            float p;
            p = expf(lrow[e + 0] - m0) * inv;
            mv.x = (e + 0 == i0 || e + 0 == i1) ? 1.0f : 0.0f; pv.x = p; rv.x = mv.x * p * rinv;
            p = expf(lrow[e + 1] - m0) * inv;
            mv.y = (e + 1 == i0 || e + 1 == i1) ? 1.0f : 0.0f; pv.y = p; rv.y = mv.y * p * rinv;
            p = expf(lrow[e + 2] - m0) * inv;
            mv.z = (e + 2 == i0 || e + 2 == i1) ? 1.0f : 0.0f; pv.z = p; rv.z = mv.z * p * rinv;
            p = expf(lrow[e + 3] - m0) * inv;
            mv.w = (e + 3 == i0 || e + 3 == i1) ? 1.0f : 0.0f; pv.w = p; rv.w = mv.w * p * rinv;

            *(float4*)(mask_o + e) = mv;
            *(float4*)(p_o    + e) = pv;
            *(float4*)(rp_o   + e) = rv;
        }
    }
}

extern "C" void kernel_launch(void* const* d_in, const int* in_sizes, int n_in,
                              void* d_out, int out_size)
{
    const float* x = (const float*)d_in[0];
    const float* W = (const float*)d_in[1];
    float* out = (float*)d_out;

    const int T = in_sizes[0] / D_DIM;      // 16384
    const int grid = T / M_TILE;            // 128

    router_mma_kernel<<<grid, THREADS, SMEM_TOTAL>>>(x, W, out, T);
}

// round 10
// speedup vs baseline: 1.3897x; 1.3897x over previous
#include <cuda_runtime.h>
#include <cstdint>
#include <math.h>

#define D_DIM   2048
#define E_DIM   64
#define TOPK    2
#define M_TILE  128
#define KC      32
#define NCHUNK  (D_DIM / KC)    /* 64 */
#define THREADS 256
#define WROW    160             /* W row stride (bytes): 40 words ≡ 8 mod 32 */
#define W_STAGE (64 * WROW)     /* 10240 */
#define AROW    144             /* A row stride (bytes): 36 words ≡ 4 mod 32 */
#define A_STAGE (M_TILE * AROW) /* 18432 */
#define A_BASE  (2 * W_STAGE)
#define SMEM_TOTAL (2 * W_STAGE + 2 * A_STAGE)  /* 57344 */
#define LG_STRIDE 65
#define TAU     2e-3f

__device__ __forceinline__ uint32_t smem_u32(const void* p) {
    uint32_t a;
    asm("{ .reg .u64 t; cvta.to.shared.u64 t, %1; cvt.u32.u64 %0, t; }" : "=r"(a) : "l"(p));
    return a;
}
__device__ __forceinline__ uint32_t f2tf32(float v) {
    uint32_t r;
    asm("cvt.rna.tf32.f32 %0, %1;" : "=r"(r) : "f"(v));
    return r;
}
__device__ __forceinline__ void mma_tf32(float* d, const uint32_t* a, uint32_t b0, uint32_t b1) {
    asm volatile(
        "mma.sync.aligned.m16n8k8.row.col.f32.tf32.tf32.f32 "
        "{%0,%1,%2,%3},{%4,%5,%6,%7},{%8,%9},{%0,%1,%2,%3};"
        : "+f"(d[0]), "+f"(d[1]), "+f"(d[2]), "+f"(d[3])
        : "r"(a[0]), "r"(a[1]), "r"(a[2]), "r"(a[3]), "r"(b0), "r"(b1));
}

extern __shared__ char smem[];

__global__ __launch_bounds__(THREADS, 1) void router_mma_kernel(
    const float* __restrict__ x, const float* __restrict__ W,
    float* __restrict__ out, int T)
{
    const uint32_t sb = smem_u32(smem);
    const int tid  = threadIdx.x;
    const int lane = tid & 31;
    const int wid  = tid >> 5;
    const int t0   = blockIdx.x * M_TILE;
    const int r    = lane >> 2;       // fragment row / expert-in-octet
    const int c    = lane & 3;        // fragment k index
    const int mq   = wid >> 1;        // m-quadrant: rows mq*32 .. +31
    const int nh   = wid & 1;         // n-half: experts nh*32 .. +31

    // ---- W loader: thread -> (expert we, k-group q of 8) ----
    const int we = tid >> 2;          // 0..63
    const int wq = tid & 3;           // 0..3
    const float* wp = W + (size_t)we * D_DIM + wq * 8;

    // ---- A loader: 4 float4 per thread, idx = tid + 256*j ----
    //      row = idx>>3 (0..127), col4 = idx&7

    float acc[2][4][4];
#pragma unroll
    for (int mt = 0; mt < 2; ++mt)
#pragma unroll
        for (int nt = 0; nt < 4; ++nt)
#pragma unroll
            for (int d = 0; d < 4; ++d) acc[mt][nt][d] = 0.f;

    float4 wv[2];       // W chunk in flight (8 k)
    float4 av[4];       // A chunk in flight (4 rows x 4 k)

#define LOAD_GL(kc)                                                           \
    {  wv[0] = *(const float4*)(wp + (kc) * KC);                              \
       wv[1] = *(const float4*)(wp + (kc) * KC + 4);                          \
       _Pragma("unroll")                                                      \
       for (int j = 0; j < 4; ++j) {                                          \
           int idx = tid + 256 * j;                                           \
           av[j] = *(const float4*)(x + (size_t)(t0 + (idx >> 3)) * D_DIM     \
                                    + (kc) * KC + (idx & 7) * 4);             \
       } }

    // W store: hi-only, word layout per g-block of 8: {h0,h4,h1,h5,h2,h6,h3,h7}
    // (pairs (c, c+4) adjacent -> consumer LDS.64). Odd-we threads issue the
    // +16 store first so each STS phase covers all 32 banks.
#define STS_STAGE(s)                                                          \
    {  float wf[8] = {wv[0].x, wv[0].y, wv[0].z, wv[0].w,                     \
                      wv[1].x, wv[1].y, wv[1].z, wv[1].w};                    \
       uint32_t h[8];                                                         \
       _Pragma("unroll")                                                      \
       for (int q = 0; q < 8; ++q) h[q] = f2tf32(wf[q]);                      \
       uint32_t wa = sb + (s) * W_STAGE + (uint32_t)(we * WROW + wq * 32);    \
       if (we & 1) {                                                          \
           asm volatile("st.shared.v4.b32 [%0], {%1,%2,%3,%4};"               \
               :: "r"(wa + 16), "r"(h[2]), "r"(h[6]), "r"(h[3]), "r"(h[7]) : "memory"); \
           asm volatile("st.shared.v4.b32 [%0], {%1,%2,%3,%4};"               \
               :: "r"(wa), "r"(h[0]), "r"(h[4]), "r"(h[1]), "r"(h[5]) : "memory"); \
       } else {                                                               \
           asm volatile("st.shared.v4.b32 [%0], {%1,%2,%3,%4};"               \
               :: "r"(wa), "r"(h[0]), "r"(h[4]), "r"(h[1]), "r"(h[5]) : "memory"); \
           asm volatile("st.shared.v4.b32 [%0], {%1,%2,%3,%4};"               \
               :: "r"(wa + 16), "r"(h[2]), "r"(h[6]), "r"(h[3]), "r"(h[7]) : "memory"); \
       }                                                                      \
       _Pragma("unroll")                                                      \
       for (int j = 0; j < 4; ++j) {                                          \
           int idx = tid + 256 * j;                                           \
           uint32_t aa = sb + A_BASE + (s) * A_STAGE                          \
                       + (uint32_t)((idx >> 3) * AROW + (idx & 7) * 16);      \
           asm volatile("st.shared.v4.b32 [%0], {%1,%2,%3,%4};"               \
               :: "r"(aa), "r"(__float_as_uint(av[j].x)), "r"(__float_as_uint(av[j].y)), \
                  "r"(__float_as_uint(av[j].z)), "r"(__float_as_uint(av[j].w)) : "memory"); \
       } }

#define COMPUTE(s)                                                            \
    {  const uint32_t wbase = sb + (s) * W_STAGE                              \
           + (uint32_t)((nh * 32 + r) * WROW + c * 8);                        \
       const uint32_t abase = sb + A_BASE + (s) * A_STAGE                     \
           + (uint32_t)((mq * 32 + r) * AROW + c * 4);                        \
       _Pragma("unroll")                                                      \
       for (int g = 0; g < 4; ++g) {                                          \
           uint32_t ah[2][4], al[2][4];                                       \
           _Pragma("unroll")                                                  \
           for (int mt = 0; mt < 2; ++mt)                                     \
           _Pragma("unroll")                                                  \
           for (int pos = 0; pos < 4; ++pos) {                                \
               uint32_t aaddr = abase                                         \
                   + (uint32_t)((mt * 16 + (pos & 1) * 8) * AROW              \
                   + g * 32 + (pos >> 1) * 16);                               \
               float v;                                                       \
               asm volatile("ld.shared.f32 %0, [%1];" : "=f"(v) : "r"(aaddr)); \
               ah[mt][pos] = f2tf32(v);                                       \
               al[mt][pos] = f2tf32(v - __uint_as_float(ah[mt][pos]));        \
           }                                                                  \
           _Pragma("unroll")                                                  \
           for (int nt = 0; nt < 4; ++nt) {                                   \
               uint32_t b0, b1;                                               \
               uint32_t baddr = wbase + (uint32_t)(nt * 8 * WROW + g * 32);   \
               asm volatile("ld.shared.v2.b32 {%0,%1}, [%2];"                 \
                   : "=r"(b0), "=r"(b1) : "r"(baddr));                        \
               mma_tf32(acc[0][nt], ah[0], b0, b1);                           \
               mma_tf32(acc[1][nt], ah[1], b0, b1);                           \
               mma_tf32(acc[0][nt], al[0], b0, b1);                           \
               mma_tf32(acc[1][nt], al[1], b0, b1);                           \
           } } }

    // -------- prologue --------
    LOAD_GL(0);
    STS_STAGE(0);
    LOAD_GL(1);
    __syncthreads();

    // -------- main loop --------
    for (int kc = 0; kc < NCHUNK; ++kc) {
        const int s = kc & 1;
        if (kc + 1 < NCHUNK) STS_STAGE(s ^ 1);   // regs hold chunk kc+1
        if (kc + 2 < NCHUNK) LOAD_GL(kc + 2);
        __syncthreads();                          // stage s^1 visible next iter
        COMPUTE(s);
        __syncthreads();                          // stage s reads done
    }

    // -------- dump logits to smem --------
    float* lg = (float*)smem;
#pragma unroll
    for (int mt = 0; mt < 2; ++mt)
#pragma unroll
        for (int nt = 0; nt < 4; ++nt) {
            int row = mq * 32 + mt * 16 + r;
            int col = nh * 32 + nt * 8 + c * 2;
            lg[row * LG_STRIDE + col]           = acc[mt][nt][0];
            lg[row * LG_STRIDE + col + 1]       = acc[mt][nt][1];
            lg[(row + 8) * LG_STRIDE + col]     = acc[mt][nt][2];
            lg[(row + 8) * LG_STRIDE + col + 1] = acc[mt][nt][3];
        }
    __syncthreads();

    // -------- per-token epilogue: threads 0..127, one per token --------
    if (tid < M_TILE) {
        const float* lrow = &lg[tid * LG_STRIDE];

        // top-4 scan ('>' keeps lower index first on ties, matching lax.top_k)
        float m0 = -INFINITY, m1 = -INFINITY, m2 = -INFINITY, m3 = -INFINITY;
        int i0 = 0, i1 = 0, i2 = 0, i3 = 0;
#pragma unroll 8
        for (int e = 0; e < E_DIM; ++e) {
            float v = lrow[e];
            if (v > m0)      { m3=m2;i3=i2; m2=m1;i2=i1; m1=m0;i1=i0; m0=v;i0=e; }
            else if (v > m1) { m3=m2;i3=i2; m2=m1;i2=i1; m1=v;i1=e; }
            else if (v > m2) { m3=m2;i3=i2; m2=v;i2=e; }
            else if (v > m3) { m3=v;i3=e; }
        }

        // fp64 fixup for near-ties (ordering becomes exact)
        bool flag = (m0 - m1 < TAU) || (m1 - m2 < TAU) || (m2 - m3 < TAU);
        unsigned bal = __ballot_sync(0xFFFFFFFFu, flag);
        while (bal) {
            int src = __ffs(bal) - 1;
            bal &= bal - 1;
            int tt = t0 + (wid << 5) + src;
            int e4[4];
            e4[0] = __shfl_sync(0xFFFFFFFFu, i0, src);
            e4[1] = __shfl_sync(0xFFFFFFFFu, i1, src);
            e4[2] = __shfl_sync(0xFFFFFFFFu, i2, src);
            e4[3] = __shfl_sync(0xFFFFFFFFu, i3, src);
            double s4[4] = {0.0, 0.0, 0.0, 0.0};
            const float* xrow2 = x + (size_t)tt * D_DIM;
            for (int k = lane; k < D_DIM; k += 32) {
                double xv = (double)xrow2[k];
#pragma unroll
                for (int j = 0; j < 4; ++j)
                    s4[j] += xv * (double)W[(size_t)e4[j] * D_DIM + k];
            }
#pragma unroll
            for (int off = 16; off > 0; off >>= 1)
#pragma unroll
                for (int j = 0; j < 4; ++j)
                    s4[j] += __shfl_xor_sync(0xFFFFFFFFu, s4[j], off);
            if (lane == src) {
                for (int a = 0; a < 3; ++a)
                    for (int b = 0; b < 3 - a; ++b)
                        if (s4[b + 1] > s4[b]) {
                            double td = s4[b]; s4[b] = s4[b + 1]; s4[b + 1] = td;
                            int ti = e4[b]; e4[b] = e4[b + 1]; e4[b + 1] = ti;
                        }
                i0 = e4[0];
                i1 = e4[1];
            }
        }

        // softmax + outputs
        float ssum = 0.f;
#pragma unroll 8
        for (int e = 0; e < E_DIM; ++e) ssum += expf(lrow[e] - m0);
        const float inv  = 1.0f / ssum;
        const float p1   = expf(lrow[i0] - m0) * inv;
        const float p2   = expf(lrow[i1] - m0) * inv;
        const float rinv = 1.0f / (p1 + p2);

        const int t = t0 + tid;
        const size_t TT = (size_t)T;
        float* mask_o = out + (size_t)t * E_DIM;
        float* idx_o  = out + TT * E_DIM + (size_t)t * TOPK;
        float* rp_o   = out + TT * (E_DIM + TOPK) + (size_t)t * E_DIM;
        float* p_o    = out + TT * (2 * E_DIM + TOPK) + (size_t)t * E_DIM;

        idx_o[0] = (float)i0;
        idx_o[1] = (float)i1;

#pragma unroll 4
        for (int e = 0; e < E_DIM; e += 4) {
            float4 pv, mv, rv;
            float p;
            p = expf(lrow[e + 0] - m0) * inv;
            mv.x = (e + 0 == i0 || e + 0 == i1) ? 1.0f : 0.0f; pv.x = p; rv.x = mv.x * p * rinv;
            p = expf(lrow[e + 1] - m0) * inv;
            mv.y = (e + 1 == i0 || e + 1 == i1) ? 1.0f : 0.0f; pv.y = p; rv.y = mv.y * p * rinv;
            p = expf(lrow[e + 2] - m0) * inv;
            mv.z = (e + 2 == i0 || e + 2 == i1) ? 1.0f : 0.0f; pv.z = p; rv.z = mv.z * p * rinv;
            p = expf(lrow[e + 3] - m0) * inv;
            mv.w = (e + 3 == i0 || e + 3 == i1) ? 1.0f : 0.0f; pv.w = p; rv.w = mv.w * p * rinv;

            *(float4*)(mask_o + e) = mv;
            *(float4*)(p_o    + e) = pv;
            *(float4*)(rp_o   + e) = rv;
        }
    }
}

extern "C" void kernel_launch(void* const* d_in, const int* in_sizes, int n_in,
                              void* d_out, int out_size)
{
    const float* x = (const float*)d_in[0];
    const float* W = (const float*)d_in[1];
    float* out = (float*)d_out;

    const int T = in_sizes[0] / D_DIM;      // 16384
    const int grid = T / M_TILE;            // 128

    cudaFuncSetAttribute(router_mma_kernel,
                         cudaFuncAttributeMaxDynamicSharedMemorySize, SMEM_TOTAL);
    router_mma_kernel<<<grid, THREADS, SMEM_TOTAL>>>(x, W, out, T);
}